// round 13
// baseline (speedup 1.0000x reference)
#include <cuda_runtime.h>
#include <cuda_fp16.h>

#define HW    512
#define IMG   (HW*HW)
#define BATCH 32
#define NTOT  (BATCH*IMG)        // per stream
#define NWARP 4096               // 64 images * 64 stripes of 8 rows
#define FULLM 0xffffffffu

// __device__ scratch (no allocation allowed)
__device__ __align__(16) __half g_h0[2*NTOT];   // image i = s*32+b
__device__ __align__(16) __half g_eA[2*NTOT];
__device__ __align__(16) __half g_eB[2*NTOT];
__device__ __align__(16) __half g_P [2*NTOT];   // running product (1-skel), fp16
__device__ double g_part[NWARP*2];

__device__ __forceinline__ int clampi(int v){ return v<0?0:(v>HW-1?HW-1:v); }

struct Row { __half2 h[8]; };    // 16 halves: lane covers gx [16*lane, 16*lane+15]

__device__ __forceinline__ unsigned h2u(__half2 x){ return *reinterpret_cast<unsigned*>(&x); }
__device__ __forceinline__ __half2  u2h(unsigned x){ return *reinterpret_cast<__half2*>(&x); }

__device__ __forceinline__ Row ld_row(const __half* base, int y, int xoff){
    const uint4* p = reinterpret_cast<const uint4*>(base + (size_t)clampi(y)*HW + xoff);
    uint4 a = p[0], b = p[1];
    Row r;
    r.h[0]=u2h(a.x); r.h[1]=u2h(a.y); r.h[2]=u2h(a.z); r.h[3]=u2h(a.w);
    r.h[4]=u2h(b.x); r.h[5]=u2h(b.y); r.h[6]=u2h(b.z); r.h[7]=u2h(b.w);
    return r;
}
__device__ __forceinline__ void st_row(__half* base, int y, int xoff, const Row& r){
    uint4 a, b;
    a.x=h2u(r.h[0]); a.y=h2u(r.h[1]); a.z=h2u(r.h[2]); a.w=h2u(r.h[3]);
    b.x=h2u(r.h[4]); b.y=h2u(r.h[5]); b.z=h2u(r.h[6]); b.w=h2u(r.h[7]);
    uint4* p = reinterpret_cast<uint4*>(base + (size_t)y*HW + xoff);
    p[0]=a; p[1]=b;
}

// horizontal 3-min (R9 style: parallel v/h, short chains); lane-boundary
// halves via shuffle; image x-edges duplicate edge element (== SAME pad).
__device__ __forceinline__ Row hmin3_row(const Row& m, int lane){
    unsigned up = __shfl_up_sync(FULLM, h2u(m.h[7]), 1);
    unsigned dn = __shfl_down_sync(FULLM, h2u(m.h[0]), 1);
    __half L = (lane==0)  ? __low2half(m.h[0])  : __high2half(u2h(up));
    __half R = (lane==31) ? __high2half(m.h[7]) : __low2half(u2h(dn));
    Row o;
    #pragma unroll
    for (int i=0;i<8;i++){
        __half a = (i==0)? L : __high2half(m.h[i-1]);
        __half b = (i==7)? R : __low2half(m.h[i+1]);
        __half2 sl = __halves2half2(a, __low2half(m.h[i]));
        __half2 sr = __halves2half2(__high2half(m.h[i]), b);
        o.h[i] = __hmin2(__hmin2(sl, m.h[i]), sr);
    }
    return o;
}
__device__ __forceinline__ Row hmax3_row(const Row& m, int lane){
    unsigned up = __shfl_up_sync(FULLM, h2u(m.h[7]), 1);
    unsigned dn = __shfl_down_sync(FULLM, h2u(m.h[0]), 1);
    __half L = (lane==0)  ? __low2half(m.h[0])  : __high2half(u2h(up));
    __half R = (lane==31) ? __high2half(m.h[7]) : __low2half(u2h(dn));
    Row o;
    #pragma unroll
    for (int i=0;i<8;i++){
        __half a = (i==0)? L : __high2half(m.h[i-1]);
        __half b = (i==7)? R : __low2half(m.h[i+1]);
        __half2 sl = __halves2half2(a, __low2half(m.h[i]));
        __half2 sr = __halves2half2(__high2half(m.h[i]), b);
        o.h[i] = __hmax2(__hmax2(sl, m.h[i]), sr);
    }
    return o;
}

// erode = min(min(up,dn), hmin3(md))  (md included via hmin3)
__device__ __forceinline__ Row erode_row(const Row& up, const Row& md, const Row& dn, int lane){
    Row h = hmin3_row(md, lane);
    Row o;
    #pragma unroll
    for (int i=0;i<8;i++)
        o.h[i] = __hmin2(__hmin2(up.h[i], dn.h[i]), h.h[i]);
    return o;
}
// dilate = 3x3 max, separable
__device__ __forceinline__ Row dilate_rows(const Row& a, const Row& b, const Row& c, int lane){
    Row v;
    #pragma unroll
    for (int i=0;i<8;i++) v.h[i] = __hmax2(__hmax2(a.h[i], b.h[i]), c.h[i]);
    return hmax3_row(v, lane);
}

// ---------------------------------------------------------------------------
__global__ void prep_kernel(const float* __restrict__ pred, const float* __restrict__ tgt) {
    int i = blockIdx.x * blockDim.x + threadIdx.x;
    int stride = gridDim.x * blockDim.x;
    const float4* p4 = (const float4*)pred;
    const float4* t4 = (const float4*)tgt;
    for (; i < NTOT/4; i += stride) {
        float4 p = p4[i];
        p.x = 1.f/(1.f+__expf(-p.x)); p.y = 1.f/(1.f+__expf(-p.y));
        p.z = 1.f/(1.f+__expf(-p.z)); p.w = 1.f/(1.f+__expf(-p.w));
        uint2 hp;
        hp.x = h2u(__floats2half2_rn(p.x, p.y));
        hp.y = h2u(__floats2half2_rn(p.z, p.w));
        *(uint2*)&g_h0[(size_t)4*i] = hp;
        float4 t = t4[i];
        uint2 ht;
        ht.x = h2u(__floats2half2_rn(t.x, t.y));
        ht.y = h2u(__floats2half2_rn(t.z, t.w));
        *(uint2*)&g_h0[(size_t)NTOT + 4*i] = ht;
    }
}

// ---------------------------------------------------------------------------
// pair_iter: two fused skeleton stages. Register-diet version:
//  - X@y RELOADED at iteration top (L1/L2 hit) instead of held 4 iterations
//  - XD loaded in-iteration (no prefetch register)
//  - d1 computed first so e1_m1 dies before e1n is born
//   e1 = erode(X); delta_a = relu(X - dilate(e1))
//   e2 = erode(e1); delta_b = relu(e1 - dilate(e2))
//   P[y] = (first ? 1 : P[y]) * (1-delta_a)*(1-delta_b)   [all fp16 math]
//   Eout[y] = e2[y]
// ---------------------------------------------------------------------------
__global__ void __launch_bounds__(128, 5)
pair_iter(const __half* __restrict__ Xin, __half* __restrict__ P,
          __half* __restrict__ Eout, int first)
{
    const int w     = blockIdx.x * 4 + (threadIdx.x >> 5);
    const int lane  = threadIdx.x & 31;
    const int image = w >> 6;              // 0..63
    const int y0    = (w & 63) << 3;       // 8-row stripe start
    const int xoff  = lane * 16;

    const __half* ptrX = Xin + (size_t)image * IMG;
    __half*       ptrP = P   + (size_t)image * IMG;
    __half*       ptrE = Eout+ (size_t)image * IMG;

    const __half2 ONE2 = __floats2half2_rn(1.f, 1.f);
    const __half2 ZERO2 = __floats2half2_rn(0.f, 0.f);

    // ---- prologue: transient X rows y0-3 .. y0+2 ----
    Row e1_m1, e1_m2, e1_0, e1_p1, e2_m1, e2_0;
    Row XB, XC;
    {
        Row x_m3 = ld_row(ptrX, y0-3, xoff);
        Row x_m2 = ld_row(ptrX, y0-2, xoff);
        Row x_m1 = ld_row(ptrX, y0-1, xoff);
        Row x0   = ld_row(ptrX, y0  , xoff);
        Row x1   = ld_row(ptrX, y0+1, xoff);
        Row x2   = ld_row(ptrX, y0+2, xoff);

        e1_0  = erode_row(x_m1, x0, x1, lane);          // e1@y0
        e1_p1 = erode_row(x0, x1, x2, lane);            // e1@y0+1
        if (y0 == 0) { e1_m1 = e1_0; e1_m2 = e1_0; }
        else {
            e1_m1 = erode_row(x_m2, x_m1, x0, lane);    // e1@y0-1
            e1_m2 = erode_row(x_m3, x_m2, x_m1, lane);  // e1@y0-2
        }
        e2_0 = erode_row(e1_m1, e1_0, e1_p1, lane);     // e2@y0
        if (y0 == 0) e2_m1 = e2_0;
        else         e2_m1 = erode_row(e1_m2, e1_m1, e1_0, lane);
        XB = x1; XC = x2;
    }

    #pragma unroll
    for (int k = 0; k < 8; ++k) {
        const int y = y0 + k;

        // X@y reload (cache hit; short lifetime) and d1 first (frees e1_m1)
        Row XA = ld_row(ptrX, y, xoff);
        Row d1 = dilate_rows(e1_m1, e1_0, e1_p1, lane);
        Row ta;
        #pragma unroll
        for (int i = 0; i < 8; i++)
            ta.h[i] = __hsub2(ONE2, __hmax2(__hsub2(XA.h[i], d1.h[i]), ZERO2));

        Row XD = ld_row(ptrX, y+3, xoff);   // in-iteration (TLP hides latency)
        Row e1n, e2n;
        if (y+2 <= HW-1) e1n = erode_row(XB, XC, XD, lane);        else e1n = e1_p1;
        if (y+1 <= HW-1) e2n = erode_row(e1_0, e1_p1, e1n, lane);  else e2n = e2_0;

        Row d2 = dilate_rows(e2_m1, e2_0, e2n, lane);

        Row pv;
        #pragma unroll
        for (int i = 0; i < 8; i++) {
            __half2 tb = __hsub2(ONE2, __hmax2(__hsub2(e1_0.h[i], d2.h[i]), ZERO2));
            pv.h[i] = __hmul2(ta.h[i], tb);
        }
        if (!first) {
            Row po = ld_row(ptrP, y, xoff);
            #pragma unroll
            for (int i = 0; i < 8; i++) pv.h[i] = __hmul2(pv.h[i], po.h[i]);
        }
        st_row(ptrP, y, xoff, pv);
        st_row(ptrE, y, xoff, e2_0);

        // rotate windows
        XB = XC; XC = XD;
        e1_m1 = e1_0; e1_0 = e1_p1; e1_p1 = e1n;
        e2_m1 = e2_0; e2_0 = e2n;
    }
}

// ---------------------------------------------------------------------------
// final_iter: last stage (delta_10) + skel + per-warp reduction.
// Same register diet: X@y is the rolling XA; X@y+2 loaded in-iteration.
//   skel[y] = 1 - P[y]*(1 - relu(X[y]-dilate(erode(X))[y]))
//   a0 = sum(skel); a1 = sum(skel * other-stream h0)
// ---------------------------------------------------------------------------
__global__ void __launch_bounds__(128, 5)
final_iter(const __half* __restrict__ Xin, const __half* __restrict__ P,
           const __half* __restrict__ H0)
{
    const int w     = blockIdx.x * 4 + (threadIdx.x >> 5);
    const int lane  = threadIdx.x & 31;
    const int image = w >> 6;
    const int y0    = (w & 63) << 3;
    const int xoff  = lane * 16;

    const __half* ptrX = Xin + (size_t)image * IMG;
    const __half* ptrP = P   + (size_t)image * IMG;
    const __half* ptrO = H0  + (size_t)(image ^ 32) * IMG;   // opposite stream

    const __half2 ONE2 = __floats2half2_rn(1.f, 1.f);
    const __half2 ZERO2 = __floats2half2_rn(0.f, 0.f);

    Row XA = ld_row(ptrX, y0,   xoff);       // X@y
    Row XB = ld_row(ptrX, y0+1, xoff);       // X@y+1
    Row e_0, e_m1;
    {
        Row x_m2 = ld_row(ptrX, y0-2, xoff);
        Row x_m1 = ld_row(ptrX, y0-1, xoff);
        e_0 = erode_row(x_m1, XA, XB, lane);             // e@y0
        if (y0 == 0) e_m1 = e_0;
        else         e_m1 = erode_row(x_m2, x_m1, XA, lane);
    }

    double a0 = 0.0, a1 = 0.0;

    #pragma unroll
    for (int k = 0; k < 8; ++k) {
        const int y = y0 + k;
        Row XC = ld_row(ptrX, y+2, xoff);    // in-iteration

        Row e_p1;
        if (y+1 <= HW-1) e_p1 = erode_row(XA, XB, XC, lane); else e_p1 = e_0;
        Row d = dilate_rows(e_m1, e_0, e_p1, lane);

        Row po = ld_row(ptrP, y, xoff);
        Row ov = ld_row(ptrO, y, xoff);

        float s0 = 0.f, s1 = 0.f;
        #pragma unroll
        for (int i = 0; i < 8; i++) {
            __half2 t  = __hsub2(ONE2, __hmax2(__hsub2(XA.h[i], d.h[i]), ZERO2));
            __half2 sk = __hsub2(ONE2, __hmul2(po.h[i], t));
            float2 skf = __half22float2(sk);
            float2 of  = __half22float2(ov.h[i]);
            s0 += skf.x + skf.y;
            s1 += skf.x*of.x + skf.y*of.y;
        }
        a0 += (double)s0;
        a1 += (double)s1;

        XA = XB; XB = XC;
        e_m1 = e_0; e_0 = e_p1;
    }

    // warp reduction (deterministic)
    #pragma unroll
    for (int off = 16; off; off >>= 1) {
        a0 += __shfl_xor_sync(FULLM, a0, off);
        a1 += __shfl_xor_sync(FULLM, a1, off);
    }
    if (lane == 0) {
        g_part[w*2 + 0] = a0;
        g_part[w*2 + 1] = a1;
    }
}

// ---------------------------------------------------------------------------
__global__ void final_sum(float* __restrict__ out)
{
    __shared__ double sh[4][256];
    int t = threadIdx.x;
    double a[4] = {0, 0, 0, 0};
    for (int i = t; i < NWARP; i += 256) {
        int s = (i >> 11) & 1;       // image = i>>6; s = image>>5
        a[2*s + 0] += g_part[i*2 + 0];
        a[2*s + 1] += g_part[i*2 + 1];
    }
    for (int k = 0; k < 4; k++) sh[k][t] = a[k];
    __syncthreads();
    for (int off = 128; off; off >>= 1) {
        if (t < off)
            for (int k = 0; k < 4; k++) sh[k][t] += sh[k][t + off];
        __syncthreads();
    }
    if (t == 0) {
        // s=0: pred-skel sums (sum skel, sum skel*target)
        // s=1: target-skel sums (sum skel, sum skel*prob)
        double tprec = (sh[1][0] + 1.0) / (sh[0][0] + 1.0);
        double tsens = (sh[3][0] + 1.0) / (sh[2][0] + 1.0);
        double cl = 2.0 * tprec * tsens / (tprec + tsens + 1e-7);
        out[0] = (float)(1.0 - cl);
    }
}

// ---------------------------------------------------------------------------
extern "C" void kernel_launch(void* const* d_in, const int* in_sizes, int n_in,
                              void* d_out, int out_size)
{
    const float* pred = (const float*)d_in[0];
    const float* tgt  = (const float*)d_in[1];

    __half *h0, *eA, *eB, *P;
    cudaGetSymbolAddress((void**)&h0, g_h0);
    cudaGetSymbolAddress((void**)&eA, g_eA);
    cudaGetSymbolAddress((void**)&eB, g_eB);
    cudaGetSymbolAddress((void**)&P,  g_P);

    prep_kernel<<<2048, 256>>>(pred, tgt);

    dim3 grid(NWARP/4);   // 1024 blocks, 4 warps each
    dim3 blk(128);

    pair_iter<<<grid, blk>>>(h0, P, eA, 1);   // d0,d1 ; out e2
    pair_iter<<<grid, blk>>>(eA, P, eB, 0);   // d2,d3 ; out e4
    pair_iter<<<grid, blk>>>(eB, P, eA, 0);   // d4,d5 ; out e6
    pair_iter<<<grid, blk>>>(eA, P, eB, 0);   // d6,d7 ; out e8
    pair_iter<<<grid, blk>>>(eB, P, eA, 0);   // d8,d9 ; out e10
    final_iter<<<grid, blk>>>(eA, P, h0);     // d10 + skel + reduction
    final_sum<<<1, 256>>>((float*)d_out);
}

// round 14
// speedup vs baseline: 1.0802x; 1.0802x over previous
#include <cuda_runtime.h>
#include <cuda_fp16.h>

#define HW    512
#define IMG   (HW*HW)
#define BATCH 32
#define NTOT  (BATCH*IMG)        // per stream
#define NWARP 8192               // 64 images * 64 stripes * 2 x-halves
#define FULLM 0xffffffffu

// seam slot rings: X rows mod 8, e1 rows mod 8, e2 rows mod 4
#define SX(y)  ((y)&7)
#define SE1(y) (8 + ((y)&7))
#define SE2(y) (16 + ((y)&3))
#define NSLOT  20

// __device__ scratch (no allocation allowed)
__device__ __align__(16) __half g_h0[2*NTOT];   // image i = s*32+b
__device__ __align__(16) __half g_eA[2*NTOT];
__device__ __align__(16) __half g_eB[2*NTOT];
__device__ __align__(16) __half g_P [2*NTOT];   // running product (1-skel), fp16
__device__ double g_part[NWARP*2];

__device__ __forceinline__ int clampi(int v){ return v<0?0:(v>HW-1?HW-1:v); }

struct Row { __half2 h[4]; };    // 8 halves: lane covers gx [xoff, xoff+8)

__device__ __forceinline__ unsigned h2u(__half2 x){ return *reinterpret_cast<unsigned*>(&x); }
__device__ __forceinline__ __half2  u2h(unsigned x){ return *reinterpret_cast<__half2*>(&x); }

__device__ __forceinline__ Row ld_row(const __half* base, int y, int xoff){
    uint4 a = *reinterpret_cast<const uint4*>(base + (size_t)clampi(y)*HW + xoff);
    Row r;
    r.h[0]=u2h(a.x); r.h[1]=u2h(a.y); r.h[2]=u2h(a.z); r.h[3]=u2h(a.w);
    return r;
}
__device__ __forceinline__ void st_row(__half* base, int y, int xoff, const Row& r){
    uint4 a;
    a.x=h2u(r.h[0]); a.y=h2u(r.h[1]); a.z=h2u(r.h[2]); a.w=h2u(r.h[3]);
    *reinterpret_cast<uint4*>(base + (size_t)y*HW + xoff) = a;
}

// seam pair layout: smb[slot*2+0] = value at gx255 (written by left warp),
//                   smb[slot*2+1] = value at gx256 (written by right warp)
__device__ __forceinline__ void put_seam(__half* smb, int slot, const Row& r,
                                         bool rh, int lane){
    if (!rh) { if (lane==31) smb[slot*2+0] = __high2half(r.h[3]); }
    else     { if (lane==0)  smb[slot*2+1] = __low2half(r.h[0]); }
}
__device__ __forceinline__ __half2 get_seam(const __half* smb, int slot){
    return *reinterpret_cast<const __half2*>(smb + slot*2);
}

// horizontal 3-min; internal lane boundaries via shuffle; team seam via the
// seam pair; image x-edges duplicate edge element (== SAME pad identity).
__device__ __forceinline__ Row hmin3_row(const Row& m, __half2 seam, bool rh, int lane){
    unsigned up = __shfl_up_sync(FULLM, h2u(m.h[3]), 1);
    unsigned dn = __shfl_down_sync(FULLM, h2u(m.h[0]), 1);
    __half L = (lane==0)  ? (rh ? __low2half(seam)  : __low2half(m.h[0]))  : __high2half(u2h(up));
    __half R = (lane==31) ? (rh ? __high2half(m.h[3]) : __high2half(seam)) : __low2half(u2h(dn));
    Row o;
    #pragma unroll
    for (int i=0;i<4;i++){
        __half a = (i==0)? L : __high2half(m.h[i-1]);
        __half b = (i==3)? R : __low2half(m.h[i+1]);
        __half2 sl = __halves2half2(a, __low2half(m.h[i]));
        __half2 sr = __halves2half2(__high2half(m.h[i]), b);
        o.h[i] = __hmin2(__hmin2(sl, m.h[i]), sr);
    }
    return o;
}
__device__ __forceinline__ Row hmax3_row(const Row& m, __half2 seam, bool rh, int lane){
    unsigned up = __shfl_up_sync(FULLM, h2u(m.h[3]), 1);
    unsigned dn = __shfl_down_sync(FULLM, h2u(m.h[0]), 1);
    __half L = (lane==0)  ? (rh ? __low2half(seam)  : __low2half(m.h[0]))  : __high2half(u2h(up));
    __half R = (lane==31) ? (rh ? __high2half(m.h[3]) : __high2half(seam)) : __low2half(u2h(dn));
    Row o;
    #pragma unroll
    for (int i=0;i<4;i++){
        __half a = (i==0)? L : __high2half(m.h[i-1]);
        __half b = (i==3)? R : __low2half(m.h[i+1]);
        __half2 sl = __halves2half2(a, __low2half(m.h[i]));
        __half2 sr = __halves2half2(__high2half(m.h[i]), b);
        o.h[i] = __hmax2(__hmax2(sl, m.h[i]), sr);
    }
    return o;
}

// erode = min(min(up,dn), hmin3(md))   (center included via hmin3)
__device__ __forceinline__ Row erode_row(const Row& up, const Row& md, const Row& dn,
                                         __half2 seam, bool rh, int lane){
    Row h = hmin3_row(md, seam, rh, lane);
    Row o;
    #pragma unroll
    for (int i=0;i<4;i++)
        o.h[i] = __hmin2(__hmin2(up.h[i], dn.h[i]), h.h[i]);
    return o;
}
// dilate = hmax3(vmax(a,b,c)); seam = elementwise max of the 3 rows' seams
__device__ __forceinline__ Row dilate_rows(const Row& a, const Row& b, const Row& c,
                                           __half2 seam, bool rh, int lane){
    Row v;
    #pragma unroll
    for (int i=0;i<4;i++) v.h[i] = __hmax2(__hmax2(a.h[i], b.h[i]), c.h[i]);
    return hmax3_row(v, seam, rh, lane);
}

// ---------------------------------------------------------------------------
__global__ void prep_kernel(const float* __restrict__ pred, const float* __restrict__ tgt) {
    int i = blockIdx.x * blockDim.x + threadIdx.x;
    int stride = gridDim.x * blockDim.x;
    const float4* p4 = (const float4*)pred;
    const float4* t4 = (const float4*)tgt;
    for (; i < NTOT/4; i += stride) {
        float4 p = p4[i];
        p.x = 1.f/(1.f+__expf(-p.x)); p.y = 1.f/(1.f+__expf(-p.y));
        p.z = 1.f/(1.f+__expf(-p.z)); p.w = 1.f/(1.f+__expf(-p.w));
        uint2 hp;
        hp.x = h2u(__floats2half2_rn(p.x, p.y));
        hp.y = h2u(__floats2half2_rn(p.z, p.w));
        *(uint2*)&g_h0[(size_t)4*i] = hp;
        float4 t = t4[i];
        uint2 ht;
        ht.x = h2u(__floats2half2_rn(t.x, t.y));
        ht.y = h2u(__floats2half2_rn(t.z, t.w));
        *(uint2*)&g_h0[(size_t)NTOT + 4*i] = ht;
    }
}

// ---------------------------------------------------------------------------
// pair_iter: two fused skeleton stages. One TEAM (2 warps) sweeps an 8-row
// stripe; each warp owns a 256-half x-half; seam via shared ring slots,
// one __syncthreads per iteration. R9 pipeline structure retained
// (X prefetched one iteration ahead; seams written from resident rows).
// ---------------------------------------------------------------------------
__global__ void __launch_bounds__(128, 5)
pair_iter(const __half* __restrict__ Xin, __half* __restrict__ P,
          __half* __restrict__ Eout, int first)
{
    __shared__ __half sm[2][NSLOT*2];
    const int tid  = threadIdx.x;
    const int lane = tid & 31;
    const int team = tid >> 6;
    const bool rh  = (tid >> 5) & 1;          // right x-half?
    const int tg   = blockIdx.x * 2 + team;   // global team 0..4095
    const int image= tg >> 6;                 // 0..63
    const int y0   = (tg & 63) << 3;          // 8-row stripe start
    const int xoff = (rh ? 256 : 0) + lane * 8;
    __half* smb = sm[team];

    const __half* ptrX = Xin + (size_t)image * IMG;
    __half*       ptrP = P   + (size_t)image * IMG;
    __half*       ptrE = Eout+ (size_t)image * IMG;

    const __half2 ONE2 = __floats2half2_rn(1.f, 1.f);
    const __half2 ZERO2 = __floats2half2_rn(0.f, 0.f);

    // ---- prologue ----
    Row x_m3 = ld_row(ptrX, y0-3, xoff);
    Row x_m2 = ld_row(ptrX, y0-2, xoff);
    Row x_m1 = ld_row(ptrX, y0-1, xoff);
    Row XA   = ld_row(ptrX, y0  , xoff);
    Row XB   = ld_row(ptrX, y0+1, xoff);
    Row XC   = ld_row(ptrX, y0+2, xoff);
    Row XD   = ld_row(ptrX, y0+3, xoff);
    put_seam(smb, SX(y0-2), x_m2, rh, lane);
    put_seam(smb, SX(y0-1), x_m1, rh, lane);
    put_seam(smb, SX(y0  ), XA,   rh, lane);
    put_seam(smb, SX(y0+1), XB,   rh, lane);
    put_seam(smb, SX(y0+2), XC,   rh, lane);
    put_seam(smb, SX(y0+3), XD,   rh, lane);
    __syncthreads();

    Row e1_0  = erode_row(x_m1, XA, XB, get_seam(smb,SX(y0)),   rh, lane);
    Row e1_p1 = erode_row(XA,  XB, XC, get_seam(smb,SX(y0+1)), rh, lane);
    Row e1_m1, e1_m2;
    if (y0) {
        e1_m1 = erode_row(x_m2, x_m1, XA,  get_seam(smb,SX(y0-1)), rh, lane);
        e1_m2 = erode_row(x_m3, x_m2, x_m1, get_seam(smb,SX(y0-2)), rh, lane);
    } else { e1_m1 = e1_0; e1_m2 = e1_0; }
    put_seam(smb, SE1(y0-1), e1_m1, rh, lane);
    put_seam(smb, SE1(y0  ), e1_0,  rh, lane);
    put_seam(smb, SE1(y0+1), e1_p1, rh, lane);
    __syncthreads();

    Row e2_0 = erode_row(e1_m1, e1_0, e1_p1, get_seam(smb,SE1(y0)), rh, lane);
    Row e2_m1 = y0 ? erode_row(e1_m2, e1_m1, e1_0, get_seam(smb,SE1(y0-1)), rh, lane)
                   : e2_0;
    put_seam(smb, SE2(y0-1), e2_m1, rh, lane);
    put_seam(smb, SE2(y0  ), e2_0,  rh, lane);
    __syncthreads();

    #pragma unroll
    for (int k = 0; k < 8; ++k) {
        const int y = y0 + k;

        st_row(ptrE, y, xoff, e2_0);
        Row po;
        if (!first) po = ld_row(ptrP, y, xoff);
        Row Xnext = ld_row(ptrX, y+4, xoff);     // consumed next iteration

        __half2 sv1 = __hmax2(__hmax2(get_seam(smb,SE1(y-1)), get_seam(smb,SE1(y))),
                              get_seam(smb,SE1(y+1)));
        Row d1 = dilate_rows(e1_m1, e1_0, e1_p1, sv1, rh, lane);
        Row ta;
        #pragma unroll
        for (int i = 0; i < 4; i++)
            ta.h[i] = __hsub2(ONE2, __hmax2(__hsub2(XA.h[i], d1.h[i]), ZERO2));

        Row e1n, e2n;
        if (y+2 <= HW-1) e1n = erode_row(XB, XC, XD, get_seam(smb,SX(y+2)), rh, lane);
        else             e1n = e1_p1;
        if (y+1 <= HW-1) e2n = erode_row(e1_0, e1_p1, e1n, get_seam(smb,SE1(y+1)), rh, lane);
        else             e2n = e2_0;

        put_seam(smb, SE1(y+2), e1n, rh, lane);
        put_seam(smb, SE2(y+1), e2n, rh, lane);
        put_seam(smb, SX(y+3),  XD,  rh, lane);
        __syncthreads();

        __half2 sv2 = __hmax2(__hmax2(get_seam(smb,SE2(y-1)), get_seam(smb,SE2(y))),
                              get_seam(smb,SE2(y+1)));
        Row d2 = dilate_rows(e2_m1, e2_0, e2n, sv2, rh, lane);

        Row pv;
        #pragma unroll
        for (int i = 0; i < 4; i++) {
            __half2 tb = __hsub2(ONE2, __hmax2(__hsub2(e1_0.h[i], d2.h[i]), ZERO2));
            pv.h[i] = __hmul2(ta.h[i], tb);
        }
        if (!first) {
            #pragma unroll
            for (int i = 0; i < 4; i++) pv.h[i] = __hmul2(pv.h[i], po.h[i]);
        }
        st_row(ptrP, y, xoff, pv);

        // rotate windows
        XA = XB; XB = XC; XC = XD; XD = Xnext;
        e1_m1 = e1_0; e1_0 = e1_p1; e1_p1 = e1n;
        e2_m1 = e2_0; e2_0 = e2n;
    }
}

// ---------------------------------------------------------------------------
// final_iter: last stage (delta_10) + skel + per-warp reduction; same team
// split and seam protocol (one __syncthreads per iteration).
// ---------------------------------------------------------------------------
__global__ void __launch_bounds__(128, 5)
final_iter(const __half* __restrict__ Xin, const __half* __restrict__ P,
           const __half* __restrict__ H0)
{
    __shared__ __half sm[2][NSLOT*2];
    const int tid  = threadIdx.x;
    const int lane = tid & 31;
    const int team = tid >> 6;
    const bool rh  = (tid >> 5) & 1;
    const int tg   = blockIdx.x * 2 + team;
    const int image= tg >> 6;
    const int y0   = (tg & 63) << 3;
    const int xoff = (rh ? 256 : 0) + lane * 8;
    __half* smb = sm[team];

    const __half* ptrX = Xin + (size_t)image * IMG;
    const __half* ptrP = P   + (size_t)image * IMG;
    const __half* ptrO = H0  + (size_t)(image ^ 32) * IMG;   // opposite stream

    const __half2 ONE2 = __floats2half2_rn(1.f, 1.f);
    const __half2 ZERO2 = __floats2half2_rn(0.f, 0.f);

    // ---- prologue ----
    Row x_m2 = ld_row(ptrX, y0-2, xoff);
    Row x_m1 = ld_row(ptrX, y0-1, xoff);
    Row XA   = ld_row(ptrX, y0,   xoff);
    Row XB   = ld_row(ptrX, y0+1, xoff);
    Row XC   = ld_row(ptrX, y0+2, xoff);
    put_seam(smb, SX(y0-1), x_m1, rh, lane);
    put_seam(smb, SX(y0  ), XA,   rh, lane);
    put_seam(smb, SX(y0+1), XB,   rh, lane);
    __syncthreads();
    Row e_0 = erode_row(x_m1, XA, XB, get_seam(smb,SX(y0)), rh, lane);
    Row e_m1 = y0 ? erode_row(x_m2, x_m1, XA, get_seam(smb,SX(y0-1)), rh, lane)
                  : e_0;
    put_seam(smb, SE1(y0-1), e_m1, rh, lane);
    put_seam(smb, SE1(y0  ), e_0,  rh, lane);
    __syncthreads();

    double a0 = 0.0, a1 = 0.0;

    #pragma unroll
    for (int k = 0; k < 8; ++k) {
        const int y = y0 + k;
        Row Xnext = ld_row(ptrX, y+3, xoff);   // consumed next iteration
        Row po = ld_row(ptrP, y, xoff);
        Row ov = ld_row(ptrO, y, xoff);

        Row e_p1;
        if (y+1 <= HW-1) e_p1 = erode_row(XA, XB, XC, get_seam(smb,SX(y+1)), rh, lane);
        else             e_p1 = e_0;
        put_seam(smb, SE1(y+1), e_p1, rh, lane);
        put_seam(smb, SX(y+2),  XC,   rh, lane);
        __syncthreads();

        __half2 sv = __hmax2(__hmax2(get_seam(smb,SE1(y-1)), get_seam(smb,SE1(y))),
                             get_seam(smb,SE1(y+1)));
        Row d = dilate_rows(e_m1, e_0, e_p1, sv, rh, lane);

        float s0 = 0.f, s1 = 0.f;
        #pragma unroll
        for (int i = 0; i < 4; i++) {
            __half2 t  = __hsub2(ONE2, __hmax2(__hsub2(XA.h[i], d.h[i]), ZERO2));
            __half2 sk = __hsub2(ONE2, __hmul2(po.h[i], t));
            float2 skf = __half22float2(sk);
            float2 of  = __half22float2(ov.h[i]);
            s0 += skf.x + skf.y;
            s1 += skf.x*of.x + skf.y*of.y;
        }
        a0 += (double)s0;
        a1 += (double)s1;

        XA = XB; XB = XC; XC = Xnext;
        e_m1 = e_0; e_0 = e_p1;
    }

    // warp reduction (deterministic)
    #pragma unroll
    for (int off = 16; off; off >>= 1) {
        a0 += __shfl_xor_sync(FULLM, a0, off);
        a1 += __shfl_xor_sync(FULLM, a1, off);
    }
    const int w = blockIdx.x * 4 + (tid >> 5);
    if (lane == 0) {
        g_part[w*2 + 0] = a0;
        g_part[w*2 + 1] = a1;
    }
}

// ---------------------------------------------------------------------------
__global__ void final_sum(float* __restrict__ out)
{
    __shared__ double sh[4][256];
    int t = threadIdx.x;
    double a[4] = {0, 0, 0, 0};
    for (int i = t; i < NWARP; i += 256) {
        int s = (i >> 12) & 1;       // w = team*2+rh; image = w>>7; s = image>>5
        a[2*s + 0] += g_part[i*2 + 0];
        a[2*s + 1] += g_part[i*2 + 1];
    }
    for (int k = 0; k < 4; k++) sh[k][t] = a[k];
    __syncthreads();
    for (int off = 128; off; off >>= 1) {
        if (t < off)
            for (int k = 0; k < 4; k++) sh[k][t] += sh[k][t + off];
        __syncthreads();
    }
    if (t == 0) {
        double tprec = (sh[1][0] + 1.0) / (sh[0][0] + 1.0);
        double tsens = (sh[3][0] + 1.0) / (sh[2][0] + 1.0);
        double cl = 2.0 * tprec * tsens / (tprec + tsens + 1e-7);
        out[0] = (float)(1.0 - cl);
    }
}

// ---------------------------------------------------------------------------
extern "C" void kernel_launch(void* const* d_in, const int* in_sizes, int n_in,
                              void* d_out, int out_size)
{
    const float* pred = (const float*)d_in[0];
    const float* tgt  = (const float*)d_in[1];

    __half *h0, *eA, *eB, *P;
    cudaGetSymbolAddress((void**)&h0, g_h0);
    cudaGetSymbolAddress((void**)&eA, g_eA);
    cudaGetSymbolAddress((void**)&eB, g_eB);
    cudaGetSymbolAddress((void**)&P,  g_P);

    prep_kernel<<<2048, 256>>>(pred, tgt);

    dim3 grid(2048);   // 2048 blocks x 2 teams = 4096 teams, 8192 warps
    dim3 blk(128);

    pair_iter<<<grid, blk>>>(h0, P, eA, 1);   // d0,d1 ; out e2
    pair_iter<<<grid, blk>>>(eA, P, eB, 0);   // d2,d3 ; out e4
    pair_iter<<<grid, blk>>>(eB, P, eA, 0);   // d4,d5 ; out e6
    pair_iter<<<grid, blk>>>(eA, P, eB, 0);   // d6,d7 ; out e8
    pair_iter<<<grid, blk>>>(eB, P, eA, 0);   // d8,d9 ; out e10
    final_iter<<<grid, blk>>>(eA, P, h0);     // d10 + skel + reduction
    final_sum<<<1, 256>>>((float*)d_out);
}